// round 1
// baseline (speedup 1.0000x reference)
#include <cuda_runtime.h>
#include <cuda_bf16.h>

// Problem constants
#define BB   2
#define SS   2048
#define DIM  2048
#define NH   16
#define KVH  4
#define HD   128
#define ROWS (BB*SS)          // 4096
#define KVD  (KVH*HD)         // 512

// ---------------------------------------------------------------------------
// Scratch (static device globals — no allocation)
// ---------------------------------------------------------------------------
__device__ float gQ[(size_t)ROWS * DIM];   // 33.5 MB
__device__ float gK[(size_t)ROWS * KVD];   //  8.4 MB
__device__ float gV[(size_t)ROWS * KVD];   //  8.4 MB
__device__ float gC[(size_t)ROWS * DIM];   // 33.5 MB (attention context)

// ---------------------------------------------------------------------------
// SGEMM: C[M,N] = A[M,K] @ B[K,N], all row-major fp32.
// 128x128 block tile, BK=8, 8x8 per-thread microtile, 256 threads.
// M,N,K all divisible by the tile sizes for this problem.
// ---------------------------------------------------------------------------
__global__ __launch_bounds__(256) void sgemm128(
    const float* __restrict__ A, const float* __restrict__ B,
    float* __restrict__ C, int M, int N, int K)
{
    __shared__ float As[8][128];
    __shared__ float Bs[8][128];

    const int bx = blockIdx.x;       // N tiles
    const int by = blockIdx.y;       // M tiles
    const int tid = threadIdx.x;
    const int tx = tid & 15;
    const int ty = tid >> 4;

    const int aRow = tid >> 1;           // 0..127
    const int aCol = (tid & 1) << 2;     // 0 or 4
    const int bRow = tid >> 5;           // 0..7
    const int bCol = (tid & 31) << 2;    // 0..124

    float acc[8][8];
    #pragma unroll
    for (int i = 0; i < 8; i++)
        #pragma unroll
        for (int j = 0; j < 8; j++) acc[i][j] = 0.f;

    const float* Ap = A + (size_t)(by * 128 + aRow) * K + aCol;
    const float* Bp = B + (size_t)bRow * N + bx * 128 + bCol;

    for (int k0 = 0; k0 < K; k0 += 8) {
        float4 a = *(const float4*)(Ap + k0);
        As[aCol + 0][aRow] = a.x;
        As[aCol + 1][aRow] = a.y;
        As[aCol + 2][aRow] = a.z;
        As[aCol + 3][aRow] = a.w;
        *(float4*)&Bs[bRow][bCol] = *(const float4*)(Bp + (size_t)k0 * N);
        __syncthreads();

        #pragma unroll
        for (int kk = 0; kk < 8; kk++) {
            float ar[8], br[8];
            #pragma unroll
            for (int i = 0; i < 8; i++) ar[i] = As[kk][ty * 8 + i];
            #pragma unroll
            for (int j = 0; j < 8; j++) br[j] = Bs[kk][tx * 8 + j];
            #pragma unroll
            for (int i = 0; i < 8; i++)
                #pragma unroll
                for (int j = 0; j < 8; j++)
                    acc[i][j] = fmaf(ar[i], br[j], acc[i][j]);
        }
        __syncthreads();
    }

    #pragma unroll
    for (int i = 0; i < 8; i++) {
        size_t row = (size_t)(by * 128 + ty * 8 + i);
        float* Cp = C + row * N + bx * 128 + tx * 8;
        *(float4*)(Cp + 0) = make_float4(acc[i][0], acc[i][1], acc[i][2], acc[i][3]);
        *(float4*)(Cp + 4) = make_float4(acc[i][4], acc[i][5], acc[i][6], acc[i][7]);
    }
}

// ---------------------------------------------------------------------------
// RoPE in-place on [rows, nheads*128]; position = row % SS.
// out[d]     = x[d]*cos[d]       - x[d+64]*sin[d]
// out[d+64]  = x[d+64]*cos[d+64] + x[d]*sin[d+64]
// ---------------------------------------------------------------------------
__global__ void rope_kernel(float* __restrict__ x,
                            const float* __restrict__ cosT,
                            const float* __restrict__ sinT,
                            int rows, int nheads)
{
    int idx = blockIdx.x * blockDim.x + threadIdx.x;
    int total = rows * nheads * 64;
    if (idx >= total) return;
    int d = idx & 63;
    int h = (idx >> 6) % nheads;
    int r = idx / (64 * nheads);
    int s = r & (SS - 1);

    float c0 = cosT[s * HD + d];
    float s0 = sinT[s * HD + d];
    float c1 = cosT[s * HD + d + 64];
    float s1 = sinT[s * HD + d + 64];

    float* p = x + (size_t)r * nheads * HD + h * HD;
    float x0 = p[d];
    float x1 = p[d + 64];
    p[d]      = x0 * c0 - x1 * s0;
    p[d + 64] = x1 * c1 + x0 * s1;
}

// ---------------------------------------------------------------------------
// Fused causal attention with online softmax.
// grid: (S/64, B*H). block: 256 threads.
// 64-query x 64-key tiles; K and V share one smem buffer (stride 132 pad).
// scores phase: 16x16 threads, 4x4 each.  PV phase: 4 rows x 8 cols each.
// ---------------------------------------------------------------------------
#define QPAD 132
#define ATTN_SMEM ((64*QPAD*2 + 64*64) * 4)

__global__ __launch_bounds__(256) void attn_kernel(
    const float* __restrict__ Qg, const float* __restrict__ Kg,
    const float* __restrict__ Vg, const float* __restrict__ alibi,
    const float* __restrict__ amask, float* __restrict__ Og)
{
    extern __shared__ float smn[];
    float* sQ  = smn;                  // 64 x 132
    float* sKV = smn + 64 * QPAD;      // 64 x 132 (K, then V)
    float* sP  = smn + 2 * 64 * QPAD;  // 64 x 64
    __shared__ float s_m[64], s_l[64], s_corr[64], s_red[64];

    const int tid = threadIdx.x;
    const int tx = tid & 15;
    const int ty = tid >> 4;
    const int bh = blockIdx.y;
    const int b = bh >> 4;
    const int h = bh & 15;
    const int kvh = h >> 2;
    const int q0 = blockIdx.x * 64;

    // load Q tile (64 x 128)
    for (int i = tid; i < 64 * 32; i += 256) {
        int r = i >> 5, c4 = (i & 31) << 2;
        *(float4*)&sQ[r * QPAD + c4] =
            *(const float4*)&Qg[((size_t)(b * SS + q0 + r)) * DIM + h * HD + c4];
    }
    if (tid < 64) { s_m[tid] = -1e30f; s_l[tid] = 0.f; }

    float oacc[4][8];
    #pragma unroll
    for (int i = 0; i < 4; i++)
        #pragma unroll
        for (int j = 0; j < 8; j++) oacc[i][j] = 0.f;
    __syncthreads();

    const float scale = 0.08838834764831845f;  // 1/sqrt(128)
    const int ktiles = q0 / 64 + 1;            // causal skip

    for (int kt = 0; kt < ktiles; kt++) {
        const int k0 = kt * 64;
        // load K tile
        for (int i = tid; i < 64 * 32; i += 256) {
            int r = i >> 5, c4 = (i & 31) << 2;
            *(float4*)&sKV[r * QPAD + c4] =
                *(const float4*)&Kg[((size_t)(b * SS + k0 + r)) * KVD + kvh * HD + c4];
        }
        __syncthreads();

        // scores 4x4 per thread
        float sc[4][4];
        #pragma unroll
        for (int i = 0; i < 4; i++)
            #pragma unroll
            for (int j = 0; j < 4; j++) sc[i][j] = 0.f;

        #pragma unroll 4
        for (int d = 0; d < HD; d++) {
            float qr[4], kr[4];
            #pragma unroll
            for (int i = 0; i < 4; i++) qr[i] = sQ[(ty * 4 + i) * QPAD + d];
            #pragma unroll
            for (int j = 0; j < 4; j++) kr[j] = sKV[(tx * 4 + j) * QPAD + d];
            #pragma unroll
            for (int i = 0; i < 4; i++)
                #pragma unroll
                for (int j = 0; j < 4; j++)
                    sc[i][j] = fmaf(qr[i], kr[j], sc[i][j]);
        }

        // scale + causal + alibi + attention_mask
        #pragma unroll
        for (int i = 0; i < 4; i++) {
            int q = q0 + ty * 4 + i;
            #pragma unroll
            for (int j = 0; j < 4; j++) {
                int k = k0 + tx * 4 + j;
                float v = sc[i][j] * scale
                        + alibi[((size_t)b * SS + q) * SS + k]
                        + amask[b * SS + k];
                if (k > q) v += -1e9f;
                sc[i][j] = v;
            }
        }

        // row max (across 16 tx lanes within half-warp)
        #pragma unroll
        for (int i = 0; i < 4; i++) {
            float m = fmaxf(fmaxf(sc[i][0], sc[i][1]), fmaxf(sc[i][2], sc[i][3]));
            m = fmaxf(m, __shfl_xor_sync(0xffffffffu, m, 1));
            m = fmaxf(m, __shfl_xor_sync(0xffffffffu, m, 2));
            m = fmaxf(m, __shfl_xor_sync(0xffffffffu, m, 4));
            m = fmaxf(m, __shfl_xor_sync(0xffffffffu, m, 8));
            if (tx == 0) s_red[ty * 4 + i] = m;
        }
        __syncthreads();  // all K reads done, s_red ready

        if (tid < 64) {
            float mo = s_m[tid];
            float mn = fmaxf(mo, s_red[tid]);
            s_corr[tid] = __expf(mo - mn);
            s_m[tid] = mn;
        }
        // load V tile (overwrites K, safe after sync)
        for (int i = tid; i < 64 * 32; i += 256) {
            int r = i >> 5, c4 = (i & 31) << 2;
            *(float4*)&sKV[r * QPAD + c4] =
                *(const float4*)&Vg[((size_t)(b * SS + k0 + r)) * KVD + kvh * HD + c4];
        }
        __syncthreads();  // s_m/s_corr visible, V in smem

        // p = exp(s - m), row sums, store P
        #pragma unroll
        for (int i = 0; i < 4; i++) {
            float m = s_m[ty * 4 + i];
            float rs = 0.f;
            #pragma unroll
            for (int j = 0; j < 4; j++) {
                float p = __expf(sc[i][j] - m);
                sP[(ty * 4 + i) * 64 + tx * 4 + j] = p;
                rs += p;
            }
            rs += __shfl_xor_sync(0xffffffffu, rs, 1);
            rs += __shfl_xor_sync(0xffffffffu, rs, 2);
            rs += __shfl_xor_sync(0xffffffffu, rs, 4);
            rs += __shfl_xor_sync(0xffffffffu, rs, 8);
            if (tx == 0) s_red[ty * 4 + i] = rs;
        }
        __syncthreads();  // sP + s_red ready

        if (tid < 64) s_l[tid] = s_l[tid] * s_corr[tid] + s_red[tid];

        // rescale O, accumulate P @ V
        #pragma unroll
        for (int i = 0; i < 4; i++) {
            float c = s_corr[ty * 4 + i];
            #pragma unroll
            for (int j = 0; j < 8; j++) oacc[i][j] *= c;
        }
        #pragma unroll 2
        for (int k = 0; k < 64; k++) {
            float pr[4];
            #pragma unroll
            for (int i = 0; i < 4; i++) pr[i] = sP[(ty * 4 + i) * 64 + k];
            float4 v0 = *(const float4*)&sKV[k * QPAD + tx * 8];
            float4 v1 = *(const float4*)&sKV[k * QPAD + tx * 8 + 4];
            float vr[8] = {v0.x, v0.y, v0.z, v0.w, v1.x, v1.y, v1.z, v1.w};
            #pragma unroll
            for (int i = 0; i < 4; i++)
                #pragma unroll
                for (int j = 0; j < 8; j++)
                    oacc[i][j] = fmaf(pr[i], vr[j], oacc[i][j]);
        }
        __syncthreads();  // release sKV/sP for next tile
    }

    // epilogue: O /= l, write ctx [B*S, H*HD]
    #pragma unroll
    for (int i = 0; i < 4; i++) {
        int q = q0 + ty * 4 + i;
        float inv = 1.0f / s_l[ty * 4 + i];
        size_t base = ((size_t)(b * SS + q)) * DIM + h * HD + tx * 8;
        *(float4*)&Og[base] =
            make_float4(oacc[i][0] * inv, oacc[i][1] * inv, oacc[i][2] * inv, oacc[i][3] * inv);
        *(float4*)&Og[base + 4] =
            make_float4(oacc[i][4] * inv, oacc[i][5] * inv, oacc[i][6] * inv, oacc[i][7] * inv);
    }
}

// ---------------------------------------------------------------------------
// Launch
// ---------------------------------------------------------------------------
extern "C" void kernel_launch(void* const* d_in, const int* in_sizes, int n_in,
                              void* d_out, int out_size)
{
    const float* X     = (const float*)d_in[0];  // [B,S,DIM]
    const float* cosT  = (const float*)d_in[1];  // [S,HD]
    const float* sinT  = (const float*)d_in[2];  // [S,HD]
    const float* alibi = (const float*)d_in[3];  // [B,S,S]
    const float* amask = (const float*)d_in[4];  // [B,1,1,S]
    const float* wq    = (const float*)d_in[5];  // [DIM,DIM]
    const float* wk    = (const float*)d_in[6];  // [DIM,KVD]
    const float* wv    = (const float*)d_in[7];  // [DIM,KVD]
    const float* wo    = (const float*)d_in[8];  // [DIM,DIM]
    float* out = (float*)d_out;

    float *Q, *K, *V, *C;
    cudaGetSymbolAddress((void**)&Q, gQ);
    cudaGetSymbolAddress((void**)&K, gK);
    cudaGetSymbolAddress((void**)&V, gV);
    cudaGetSymbolAddress((void**)&C, gC);

    cudaFuncSetAttribute(attn_kernel,
                         cudaFuncAttributeMaxDynamicSharedMemorySize, ATTN_SMEM);

    // projections
    sgemm128<<<dim3(DIM / 128, ROWS / 128), 256>>>(X, wq, Q, ROWS, DIM, DIM);
    sgemm128<<<dim3(KVD / 128, ROWS / 128), 256>>>(X, wk, K, ROWS, KVD, DIM);
    sgemm128<<<dim3(KVD / 128, ROWS / 128), 256>>>(X, wv, V, ROWS, KVD, DIM);

    // RoPE on Q and K
    {
        int totQ = ROWS * NH * 64;
        rope_kernel<<<(totQ + 255) / 256, 256>>>(Q, cosT, sinT, ROWS, NH);
        int totK = ROWS * KVH * 64;
        rope_kernel<<<(totK + 255) / 256, 256>>>(K, cosT, sinT, ROWS, KVH);
    }

    // fused attention
    attn_kernel<<<dim3(SS / 64, BB * NH), 256, ATTN_SMEM>>>(Q, K, V, alibi, amask, C);

    // output projection
    sgemm128<<<dim3(DIM / 128, ROWS / 128), 256>>>(C, wo, out, ROWS, DIM, DIM);
}

// round 2
// speedup vs baseline: 2.2322x; 2.2322x over previous
#include <cuda_runtime.h>
#include <cuda_bf16.h>
#include <cstdint>

// Problem constants
#define BB   2
#define SS   2048
#define DIM  2048
#define NH   16
#define KVH  4
#define HD   128
#define ROWS (BB*SS)          // 4096
#define KVD  (KVH*HD)         // 512

// ---------------------------------------------------------------------------
// Scratch (static device globals — no allocation)
// ---------------------------------------------------------------------------
__device__ float gQ [(size_t)ROWS * DIM];
__device__ float gK [(size_t)ROWS * KVD];
__device__ float gV [(size_t)ROWS * KVD];
__device__ float gC [(size_t)ROWS * DIM];
__device__ float gXr[(size_t)ROWS * DIM];   // tf32-rounded inputs
__device__ float gWqr[(size_t)DIM * DIM];
__device__ float gWkr[(size_t)DIM * KVD];
__device__ float gWvr[(size_t)DIM * KVD];
__device__ float gWor[(size_t)DIM * DIM];

// ---------------------------------------------------------------------------
// tf32 rounding helpers
// ---------------------------------------------------------------------------
__device__ __forceinline__ float tf32r(float x) {
    unsigned u;
    asm("cvt.rna.tf32.f32 %0, %1;" : "=r"(u) : "f"(x));
    return __uint_as_float(u);
}

__global__ void round_tf32_k(const float* __restrict__ in,
                             float* __restrict__ out, int n4) {
    int i = blockIdx.x * blockDim.x + threadIdx.x;
    if (i >= n4) return;
    float4 v = ((const float4*)in)[i];
    v.x = tf32r(v.x); v.y = tf32r(v.y); v.z = tf32r(v.z); v.w = tf32r(v.w);
    ((float4*)out)[i] = v;
}

// ---------------------------------------------------------------------------
// TF32 tensor-core GEMM: C[M,N] = A[M,K] @ B[K,N], row-major fp32 storage
// holding tf32-rounded values. 128x128 block, BK=32, 256 threads (8 warps,
// 2m x 4n, warp tile 64x32). cp.async double-buffered.
// ---------------------------------------------------------------------------
#define AST 36     // A smem row stride (floats): bank = 4g+l -> conflict-free
#define BST 136    // B smem row stride: bank = 8l+g -> conflict-free
#define GEMM_SMEM ((2*128*AST + 2*32*BST) * 4)   // 71680 B

__device__ __forceinline__ void cp16(unsigned dst, const void* src) {
    asm volatile("cp.async.cg.shared.global [%0], [%1], 16;\n"
                 :: "r"(dst), "l"(src));
}

__global__ __launch_bounds__(256) void tf32_gemm(
    const float* __restrict__ A, const float* __restrict__ B,
    float* __restrict__ C, int N, int K)
{
    extern __shared__ float sm[];
    float* As = sm;                    // [2][128][AST]
    float* Bs = sm + 2 * 128 * AST;    // [2][32][BST]

    const int tid  = threadIdx.x;
    const int lane = tid & 31;
    const int wid  = tid >> 5;
    const int g    = lane >> 2;        // group 0..7
    const int l    = lane & 3;         // 0..3
    const int wm   = (wid >> 2) * 64;  // warp m offset
    const int wn   = (wid & 3) * 32;   // warp n offset
    const long bm  = (long)blockIdx.y * 128;
    const long bn  = (long)blockIdx.x * 128;

    const int arow = tid >> 3, acol = (tid & 7) << 2;   // + 32*r rows
    const int brow = tid >> 5, bcol = (tid & 31) << 2;  // + 8*r rows

    const unsigned sA = (unsigned)__cvta_generic_to_shared(As);
    const unsigned sB = (unsigned)__cvta_generic_to_shared(Bs);

    float acc[16][4];
    #pragma unroll
    for (int i = 0; i < 16; i++)
        #pragma unroll
        for (int j = 0; j < 4; j++) acc[i][j] = 0.f;

    const int niter = K / 32;

    // issue tile 'it' into buffer 'buf'
    auto issue = [&](int it, int buf) {
        long k0 = (long)it * 32;
        #pragma unroll
        for (int r = 0; r < 4; r++) {
            int row = arow + 32 * r;
            cp16(sA + (unsigned)(((buf * 128 + row) * AST + acol) * 4),
                 A + (bm + row) * K + k0 + acol);
        }
        #pragma unroll
        for (int r = 0; r < 4; r++) {
            int row = brow + 8 * r;
            cp16(sB + (unsigned)(((buf * 32 + row) * BST + bcol) * 4),
                 B + (k0 + row) * N + bn + bcol);
        }
        asm volatile("cp.async.commit_group;\n");
    };

    issue(0, 0);

    for (int it = 0; it < niter; it++) {
        const int buf = it & 1;
        if (it + 1 < niter) {
            issue(it + 1, buf ^ 1);
            asm volatile("cp.async.wait_group 1;\n");
        } else {
            asm volatile("cp.async.wait_group 0;\n");
        }
        __syncthreads();

        const float* Ab = As + buf * 128 * AST;
        const float* Bb = Bs + buf * 32 * BST;

        #pragma unroll
        for (int kk = 0; kk < 4; kk++) {
            unsigned af[4][4], bf[4][2];
            #pragma unroll
            for (int mt = 0; mt < 4; mt++) {
                const float* p = Ab + (wm + mt * 16 + g) * AST + kk * 8 + l;
                af[mt][0] = __float_as_uint(p[0]);
                af[mt][1] = __float_as_uint(p[8 * AST]);
                af[mt][2] = __float_as_uint(p[4]);
                af[mt][3] = __float_as_uint(p[8 * AST + 4]);
            }
            #pragma unroll
            for (int nt = 0; nt < 4; nt++) {
                const float* p = Bb + (kk * 8 + l) * BST + wn + nt * 8 + g;
                bf[nt][0] = __float_as_uint(p[0]);
                bf[nt][1] = __float_as_uint(p[4 * BST]);
            }
            #pragma unroll
            for (int mt = 0; mt < 4; mt++)
                #pragma unroll
                for (int nt = 0; nt < 4; nt++) {
                    float* c = acc[mt * 4 + nt];
                    asm volatile(
                        "mma.sync.aligned.m16n8k8.row.col.f32.tf32.tf32.f32 "
                        "{%0,%1,%2,%3}, {%4,%5,%6,%7}, {%8,%9}, {%0,%1,%2,%3};\n"
                        : "+f"(c[0]), "+f"(c[1]), "+f"(c[2]), "+f"(c[3])
                        : "r"(af[mt][0]), "r"(af[mt][1]),
                          "r"(af[mt][2]), "r"(af[mt][3]),
                          "r"(bf[nt][0]), "r"(bf[nt][1]));
                }
        }
        __syncthreads();
    }

    // epilogue
    #pragma unroll
    for (int mt = 0; mt < 4; mt++)
        #pragma unroll
        for (int nt = 0; nt < 4; nt++) {
            const float* c = acc[mt * 4 + nt];
            long row = bm + wm + mt * 16 + g;
            long col = bn + wn + nt * 8 + 2 * l;
            *(float2*)&C[row * N + col]       = make_float2(c[0], c[1]);
            *(float2*)&C[(row + 8) * N + col] = make_float2(c[2], c[3]);
        }
}

// ---------------------------------------------------------------------------
// RoPE in-place on [rows, nheads*128]; position = row % SS.
// ---------------------------------------------------------------------------
__global__ void rope_kernel(float* __restrict__ x,
                            const float* __restrict__ cosT,
                            const float* __restrict__ sinT,
                            int rows, int nheads)
{
    int idx = blockIdx.x * blockDim.x + threadIdx.x;
    int total = rows * nheads * 64;
    if (idx >= total) return;
    int d = idx & 63;
    int h = (idx >> 6) % nheads;
    int r = idx / (64 * nheads);
    int s = r & (SS - 1);

    float c0 = cosT[s * HD + d];
    float s0 = sinT[s * HD + d];
    float c1 = cosT[s * HD + d + 64];
    float s1 = sinT[s * HD + d + 64];

    float* p = x + (size_t)r * nheads * HD + h * HD;
    float x0 = p[d];
    float x1 = p[d + 64];
    p[d]      = x0 * c0 - x1 * s0;
    p[d + 64] = x1 * c1 + x0 * s1;
}

// ---------------------------------------------------------------------------
// Fused causal attention with online softmax (fp32 math).
// K tile stored TRANSPOSED + XOR-swizzled in smem: conflict-free scatter
// stores and conflict-free float4 fragment reads. Output rounded to tf32.
// ---------------------------------------------------------------------------
#define QST  132
#define KTST 68
#define PST  68
#define ATTN_SMEM ((64*QST + 128*KTST + 64*PST) * 4)   // 86016 B

__device__ __forceinline__ int ktx(int d, int r) {
    // physical index of logical (d, r); XOR swizzle keeps 4-aligned groups
    return d * KTST + (r ^ (((d >> 2) & 7) << 2));
}

__global__ __launch_bounds__(256) void attn_kernel(
    const float* __restrict__ Qg, const float* __restrict__ Kg,
    const float* __restrict__ Vg, const float* __restrict__ alibi,
    const float* __restrict__ amask, float* __restrict__ Og)
{
    extern __shared__ float smn[];
    float* sQ  = smn;                    // [64][132] row-major Q
    float* sKV = smn + 64 * QST;         // KT [128][68] swizzled, or V [64][132]
    float* sP  = sKV + 128 * KTST;       // [64][68]
    __shared__ float s_m[64], s_l[64], s_corr[64], s_red[64];

    const int tid = threadIdx.x;
    const int tx = tid & 15;
    const int ty = tid >> 4;
    const int bh = blockIdx.y;
    const int b = bh >> 4;
    const int h = bh & 15;
    const int kvh = h >> 2;
    const int q0 = blockIdx.x * 64;

    // load Q tile (64 x 128), row-major
    for (int i = tid; i < 64 * 32; i += 256) {
        int r = i >> 5, c4 = (i & 31) << 2;
        *(float4*)&sQ[r * QST + c4] =
            *(const float4*)&Qg[((size_t)(b * SS + q0 + r)) * DIM + h * HD + c4];
    }
    if (tid < 64) { s_m[tid] = -1e30f; s_l[tid] = 0.f; }

    float oacc[4][8];
    #pragma unroll
    for (int i = 0; i < 4; i++)
        #pragma unroll
        for (int j = 0; j < 8; j++) oacc[i][j] = 0.f;
    __syncthreads();

    const float scale = 0.08838834764831845f;  // 1/sqrt(128)
    const int ktiles = q0 / 64 + 1;            // causal skip

    for (int kt = 0; kt < ktiles; kt++) {
        const int k0 = kt * 64;

        // load K tile transposed + swizzled
        for (int i = tid; i < 64 * 32; i += 256) {
            int r = i >> 5, c4 = (i & 31) << 2;
            float4 kv = *(const float4*)
                &Kg[((size_t)(b * SS + k0 + r)) * KVD + kvh * HD + c4];
            sKV[ktx(c4 + 0, r)] = kv.x;
            sKV[ktx(c4 + 1, r)] = kv.y;
            sKV[ktx(c4 + 2, r)] = kv.z;
            sKV[ktx(c4 + 3, r)] = kv.w;
        }
        __syncthreads();

        // scores: 4x4 per thread, vectorized over d
        float sc[4][4];
        #pragma unroll
        for (int i = 0; i < 4; i++)
            #pragma unroll
            for (int j = 0; j < 4; j++) sc[i][j] = 0.f;

        for (int d4 = 0; d4 < HD; d4 += 4) {
            float qv[4][4];
            #pragma unroll
            for (int i = 0; i < 4; i++)
                *(float4*)qv[i] = *(const float4*)&sQ[(ty * 4 + i) * QST + d4];
            #pragma unroll
            for (int t = 0; t < 4; t++) {
                float4 kf = *(const float4*)&sKV[ktx(d4 + t, tx * 4)];
                #pragma unroll
                for (int i = 0; i < 4; i++) {
                    sc[i][0] = fmaf(qv[i][t], kf.x, sc[i][0]);
                    sc[i][1] = fmaf(qv[i][t], kf.y, sc[i][1]);
                    sc[i][2] = fmaf(qv[i][t], kf.z, sc[i][2]);
                    sc[i][3] = fmaf(qv[i][t], kf.w, sc[i][3]);
                }
            }
        }

        // scale + causal + alibi + attention_mask (float4 loads)
        {
            float4 am = *(const float4*)&amask[b * SS + k0 + tx * 4];
            const float amv[4] = {am.x, am.y, am.z, am.w};
            #pragma unroll
            for (int i = 0; i < 4; i++) {
                int q = q0 + ty * 4 + i;
                float4 al = *(const float4*)
                    &alibi[((size_t)b * SS + q) * SS + k0 + tx * 4];
                const float alv[4] = {al.x, al.y, al.z, al.w};
                #pragma unroll
                for (int j = 0; j < 4; j++) {
                    int k = k0 + tx * 4 + j;
                    float v = sc[i][j] * scale + alv[j] + amv[j];
                    if (k > q) v += -1e9f;
                    sc[i][j] = v;
                }
            }
        }

        // row max across 16 tx lanes
        #pragma unroll
        for (int i = 0; i < 4; i++) {
            float m = fmaxf(fmaxf(sc[i][0], sc[i][1]), fmaxf(sc[i][2], sc[i][3]));
            m = fmaxf(m, __shfl_xor_sync(0xffffffffu, m, 1));
            m = fmaxf(m, __shfl_xor_sync(0xffffffffu, m, 2));
            m = fmaxf(m, __shfl_xor_sync(0xffffffffu, m, 4));
            m = fmaxf(m, __shfl_xor_sync(0xffffffffu, m, 8));
            if (tx == 0) s_red[ty * 4 + i] = m;
        }
        __syncthreads();  // all K reads done, s_red ready

        if (tid < 64) {
            float mo = s_m[tid];
            float mn = fmaxf(mo, s_red[tid]);
            s_corr[tid] = __expf(mo - mn);
            s_m[tid] = mn;
        }
        // load V tile row-major (overwrites KT buffer, safe after sync)
        for (int i = tid; i < 64 * 32; i += 256) {
            int r = i >> 5, c4 = (i & 31) << 2;
            *(float4*)&sKV[r * QST + c4] =
                *(const float4*)&Vg[((size_t)(b * SS + k0 + r)) * KVD + kvh * HD + c4];
        }
        __syncthreads();  // s_m/s_corr visible, V in smem

        // p = exp(s - m), row sums, store P
        #pragma unroll
        for (int i = 0; i < 4; i++) {
            float m = s_m[ty * 4 + i];
            float p0 = __expf(sc[i][0] - m);
            float p1 = __expf(sc[i][1] - m);
            float p2 = __expf(sc[i][2] - m);
            float p3 = __expf(sc[i][3] - m);
            *(float4*)&sP[(ty * 4 + i) * PST + tx * 4] = make_float4(p0, p1, p2, p3);
            float rs = (p0 + p1) + (p2 + p3);
            rs += __shfl_xor_sync(0xffffffffu, rs, 1);
            rs += __shfl_xor_sync(0xffffffffu, rs, 2);
            rs += __shfl_xor_sync(0xffffffffu, rs, 4);
            rs += __shfl_xor_sync(0xffffffffu, rs, 8);
            if (tx == 0) s_red[ty * 4 + i] = rs;
        }
        __syncthreads();  // sP + s_red ready

        if (tid < 64) s_l[tid] = s_l[tid] * s_corr[tid] + s_red[tid];

        // rescale O, accumulate P @ V
        #pragma unroll
        for (int i = 0; i < 4; i++) {
            float c = s_corr[ty * 4 + i];
            #pragma unroll
            for (int j = 0; j < 8; j++) oacc[i][j] *= c;
        }
        #pragma unroll 2
        for (int k = 0; k < 64; k++) {
            float pr[4];
            #pragma unroll
            for (int i = 0; i < 4; i++) pr[i] = sP[(ty * 4 + i) * PST + k];
            float4 v0 = *(const float4*)&sKV[k * QST + tx * 8];
            float4 v1 = *(const float4*)&sKV[k * QST + tx * 8 + 4];
            float vr[8] = {v0.x, v0.y, v0.z, v0.w, v1.x, v1.y, v1.z, v1.w};
            #pragma unroll
            for (int i = 0; i < 4; i++)
                #pragma unroll
                for (int j = 0; j < 8; j++)
                    oacc[i][j] = fmaf(pr[i], vr[j], oacc[i][j]);
        }
        __syncthreads();  // release sKV/sP for next tile
    }

    // epilogue: O /= l, round to tf32 (feeds tf32 Wo GEMM), write ctx
    #pragma unroll
    for (int i = 0; i < 4; i++) {
        int q = q0 + ty * 4 + i;
        float inv = 1.0f / s_l[ty * 4 + i];
        size_t base = ((size_t)(b * SS + q)) * DIM + h * HD + tx * 8;
        float o[8];
        #pragma unroll
        for (int j = 0; j < 8; j++) o[j] = tf32r(oacc[i][j] * inv);
        *(float4*)&Og[base]     = make_float4(o[0], o[1], o[2], o[3]);
        *(float4*)&Og[base + 4] = make_float4(o[4], o[5], o[6], o[7]);
    }
}

// ---------------------------------------------------------------------------
// Launch
// ---------------------------------------------------------------------------
extern "C" void kernel_launch(void* const* d_in, const int* in_sizes, int n_in,
                              void* d_out, int out_size)
{
    const float* X     = (const float*)d_in[0];
    const float* cosT  = (const float*)d_in[1];
    const float* sinT  = (const float*)d_in[2];
    const float* alibi = (const float*)d_in[3];
    const float* amask = (const float*)d_in[4];
    const float* wq    = (const float*)d_in[5];
    const float* wk    = (const float*)d_in[6];
    const float* wv    = (const float*)d_in[7];
    const float* wo    = (const float*)d_in[8];
    float* out = (float*)d_out;

    float *Q, *K, *V, *C, *Xr, *Wqr, *Wkr, *Wvr, *Wor;
    cudaGetSymbolAddress((void**)&Q,   gQ);
    cudaGetSymbolAddress((void**)&K,   gK);
    cudaGetSymbolAddress((void**)&V,   gV);
    cudaGetSymbolAddress((void**)&C,   gC);
    cudaGetSymbolAddress((void**)&Xr,  gXr);
    cudaGetSymbolAddress((void**)&Wqr, gWqr);
    cudaGetSymbolAddress((void**)&Wkr, gWkr);
    cudaGetSymbolAddress((void**)&Wvr, gWvr);
    cudaGetSymbolAddress((void**)&Wor, gWor);

    cudaFuncSetAttribute(tf32_gemm,
                         cudaFuncAttributeMaxDynamicSharedMemorySize, GEMM_SMEM);
    cudaFuncSetAttribute(attn_kernel,
                         cudaFuncAttributeMaxDynamicSharedMemorySize, ATTN_SMEM);

    // round inputs/weights to tf32 (exact truncation inside MMA afterwards)
    round_tf32_k<<<(ROWS*DIM/4 + 255)/256, 256>>>(X,  Xr,  ROWS*DIM/4);
    round_tf32_k<<<(DIM*DIM/4 + 255)/256, 256>>>(wq, Wqr, DIM*DIM/4);
    round_tf32_k<<<(DIM*KVD/4 + 255)/256, 256>>>(wk, Wkr, DIM*KVD/4);
    round_tf32_k<<<(DIM*KVD/4 + 255)/256, 256>>>(wv, Wvr, DIM*KVD/4);
    round_tf32_k<<<(DIM*DIM/4 + 255)/256, 256>>>(wo, Wor, DIM*DIM/4);

    // projections (tf32 tensor cores)
    tf32_gemm<<<dim3(DIM/128, ROWS/128), 256, GEMM_SMEM>>>(Xr, Wqr, Q, DIM, DIM);
    tf32_gemm<<<dim3(KVD/128, ROWS/128), 256, GEMM_SMEM>>>(Xr, Wkr, K, KVD, DIM);
    tf32_gemm<<<dim3(KVD/128, ROWS/128), 256, GEMM_SMEM>>>(Xr, Wvr, V, KVD, DIM);

    // RoPE on Q and K
    {
        int totQ = ROWS * NH * 64;
        rope_kernel<<<(totQ + 255)/256, 256>>>(Q, cosT, sinT, ROWS, NH);
        int totK = ROWS * KVH * 64;
        rope_kernel<<<(totK + 255)/256, 256>>>(K, cosT, sinT, ROWS, KVH);
    }

    // fused attention (fp32 math, tf32-rounded output)
    attn_kernel<<<dim3(SS/64, BB*NH), 256, ATTN_SMEM>>>(Q, K, V, alibi, amask, C);

    // output projection
    tf32_gemm<<<dim3(DIM/128, ROWS/128), 256, GEMM_SMEM>>>(C, Wor, out, DIM, DIM);
}

// round 3
// speedup vs baseline: 4.6848x; 2.0988x over previous
#include <cuda_runtime.h>
#include <cstdint>

// Problem constants
#define BB   2
#define SS   2048
#define DIM  2048
#define NH   16
#define KVH  4
#define HD   128
#define ROWS (BB*SS)          // 4096
#define QKVD 3072             // fused Q|K|V width
#define KOFF 2048
#define VOFF 2560

// ---------------------------------------------------------------------------
// Scratch (static device globals — no allocation)
// ---------------------------------------------------------------------------
__device__ float gXr  [(size_t)ROWS * DIM];
__device__ float gWqkv[(size_t)DIM * QKVD];
__device__ float gWor [(size_t)DIM * DIM];
__device__ float gQKV [(size_t)ROWS * QKVD];
__device__ float gC   [(size_t)ROWS * DIM];

// ---------------------------------------------------------------------------
// helpers
// ---------------------------------------------------------------------------
__device__ __forceinline__ unsigned tf32u(float x) {
    unsigned u;
    asm("cvt.rna.tf32.f32 %0, %1;" : "=r"(u) : "f"(x));
    return u;
}
__device__ __forceinline__ float tf32f(float x) { return __uint_as_float(tf32u(x)); }
__device__ __forceinline__ float ex2(float x) {
    float r;
    asm("ex2.approx.ftz.f32 %0, %1;" : "=f"(r) : "f"(x));
    return r;
}

__global__ void round_tf32_k(const float* __restrict__ in,
                             float* __restrict__ out, int n4) {
    int i = blockIdx.x * blockDim.x + threadIdx.x;
    if (i >= n4) return;
    float4 v = ((const float4*)in)[i];
    v.x = tf32f(v.x); v.y = tf32f(v.y); v.z = tf32f(v.z); v.w = tf32f(v.w);
    ((float4*)out)[i] = v;
}

// pack wq|wk|wv -> [DIM, 3072], tf32-rounded
__global__ void pack_wqkv(const float* __restrict__ wq,
                          const float* __restrict__ wk,
                          const float* __restrict__ wv,
                          float* __restrict__ out) {
    int i = blockIdx.x * blockDim.x + threadIdx.x;   // float4 index
    if (i >= DIM * QKVD / 4) return;
    int c = (i % (QKVD / 4)) * 4;
    int r = i / (QKVD / 4);
    const float* src;
    if (c < KOFF)       src = wq + (size_t)r * DIM + c;
    else if (c < VOFF)  src = wk + (size_t)r * 512 + (c - KOFF);
    else                src = wv + (size_t)r * 512 + (c - VOFF);
    float4 v = *(const float4*)src;
    v.x = tf32f(v.x); v.y = tf32f(v.y); v.z = tf32f(v.z); v.w = tf32f(v.w);
    ((float4*)out)[i] = v;
}

// ---------------------------------------------------------------------------
// TF32 tensor-core GEMM (unchanged from R1, known-good)
// ---------------------------------------------------------------------------
#define AST 36
#define BST 136
#define GEMM_SMEM ((2*128*AST + 2*32*BST) * 4)

__device__ __forceinline__ void cp16(unsigned dst, const void* src) {
    asm volatile("cp.async.cg.shared.global [%0], [%1], 16;\n"
                 :: "r"(dst), "l"(src));
}

__global__ __launch_bounds__(256) void tf32_gemm(
    const float* __restrict__ A, const float* __restrict__ B,
    float* __restrict__ C, int N, int K)
{
    extern __shared__ float sm[];
    float* As = sm;
    float* Bs = sm + 2 * 128 * AST;

    const int tid  = threadIdx.x;
    const int lane = tid & 31;
    const int wid  = tid >> 5;
    const int g    = lane >> 2;
    const int l    = lane & 3;
    const int wm   = (wid >> 2) * 64;
    const int wn   = (wid & 3) * 32;
    const long bm  = (long)blockIdx.y * 128;
    const long bn  = (long)blockIdx.x * 128;

    const int arow = tid >> 3, acol = (tid & 7) << 2;
    const int brow = tid >> 5, bcol = (tid & 31) << 2;

    const unsigned sA = (unsigned)__cvta_generic_to_shared(As);
    const unsigned sB = (unsigned)__cvta_generic_to_shared(Bs);

    float acc[16][4];
    #pragma unroll
    for (int i = 0; i < 16; i++)
        #pragma unroll
        for (int j = 0; j < 4; j++) acc[i][j] = 0.f;

    const int niter = K / 32;

    auto issue = [&](int it, int buf) {
        long k0 = (long)it * 32;
        #pragma unroll
        for (int r = 0; r < 4; r++) {
            int row = arow + 32 * r;
            cp16(sA + (unsigned)(((buf * 128 + row) * AST + acol) * 4),
                 A + (bm + row) * K + k0 + acol);
        }
        #pragma unroll
        for (int r = 0; r < 4; r++) {
            int row = brow + 8 * r;
            cp16(sB + (unsigned)(((buf * 32 + row) * BST + bcol) * 4),
                 B + (k0 + row) * N + bn + bcol);
        }
        asm volatile("cp.async.commit_group;\n");
    };

    issue(0, 0);

    for (int it = 0; it < niter; it++) {
        const int buf = it & 1;
        if (it + 1 < niter) {
            issue(it + 1, buf ^ 1);
            asm volatile("cp.async.wait_group 1;\n");
        } else {
            asm volatile("cp.async.wait_group 0;\n");
        }
        __syncthreads();

        const float* Ab = As + buf * 128 * AST;
        const float* Bb = Bs + buf * 32 * BST;

        #pragma unroll
        for (int kk = 0; kk < 4; kk++) {
            unsigned af[4][4], bf[4][2];
            #pragma unroll
            for (int mt = 0; mt < 4; mt++) {
                const float* p = Ab + (wm + mt * 16 + g) * AST + kk * 8 + l;
                af[mt][0] = __float_as_uint(p[0]);
                af[mt][1] = __float_as_uint(p[8 * AST]);
                af[mt][2] = __float_as_uint(p[4]);
                af[mt][3] = __float_as_uint(p[8 * AST + 4]);
            }
            #pragma unroll
            for (int nt = 0; nt < 4; nt++) {
                const float* p = Bb + (kk * 8 + l) * BST + wn + nt * 8 + g;
                bf[nt][0] = __float_as_uint(p[0]);
                bf[nt][1] = __float_as_uint(p[4 * BST]);
            }
            #pragma unroll
            for (int mt = 0; mt < 4; mt++)
                #pragma unroll
                for (int nt = 0; nt < 4; nt++) {
                    float* c = acc[mt * 4 + nt];
                    asm volatile(
                        "mma.sync.aligned.m16n8k8.row.col.f32.tf32.tf32.f32 "
                        "{%0,%1,%2,%3}, {%4,%5,%6,%7}, {%8,%9}, {%0,%1,%2,%3};\n"
                        : "+f"(c[0]), "+f"(c[1]), "+f"(c[2]), "+f"(c[3])
                        : "r"(af[mt][0]), "r"(af[mt][1]),
                          "r"(af[mt][2]), "r"(af[mt][3]),
                          "r"(bf[nt][0]), "r"(bf[nt][1]));
                }
        }
        __syncthreads();
    }

    #pragma unroll
    for (int mt = 0; mt < 4; mt++)
        #pragma unroll
        for (int nt = 0; nt < 4; nt++) {
            const float* c = acc[mt * 4 + nt];
            long row = bm + wm + mt * 16 + g;
            long col = bn + wn + nt * 8 + 2 * l;
            *(float2*)&C[row * N + col]       = make_float2(c[0], c[1]);
            *(float2*)&C[(row + 8) * N + col] = make_float2(c[2], c[3]);
        }
}

// ---------------------------------------------------------------------------
// RoPE in-place, strided buffer; ptr points at the first head column.
// ---------------------------------------------------------------------------
__global__ void rope_kernel(float* __restrict__ x,
                            const float* __restrict__ cosT,
                            const float* __restrict__ sinT,
                            int nh_shift, int stride)
{
    int idx = blockIdx.x * blockDim.x + threadIdx.x;
    int nheads = 1 << nh_shift;
    int total = ROWS * nheads * 64;
    if (idx >= total) return;
    int d = idx & 63;
    int h = (idx >> 6) & (nheads - 1);
    int r = idx >> (6 + nh_shift);
    int s = r & (SS - 1);

    float c0 = cosT[s * HD + d];
    float s0 = sinT[s * HD + d];
    float c1 = cosT[s * HD + d + 64];
    float s1 = sinT[s * HD + d + 64];

    float* p = x + (size_t)r * stride + h * HD;
    float x0 = p[d];
    float x1 = p[d + 64];
    p[d]      = x0 * c0 - x1 * s0;
    p[d + 64] = x1 * c1 + x0 * s1;
}

// ---------------------------------------------------------------------------
// Tensor-core flash attention (tf32 MMA, fp32 accum, online softmax on frags)
// Block: 128 threads (4 warps), 64 q-rows (16 per warp), 64-key tiles.
// ---------------------------------------------------------------------------
#define KST 132
#define VST 136
#define PST 68
#define ATTN_SMEM ((64*KST + 64*VST + 64*PST) * 4)   // 86016 B

__device__ __forceinline__ void mma8(float* c, const unsigned* a,
                                     unsigned b0, unsigned b1) {
    asm volatile(
        "mma.sync.aligned.m16n8k8.row.col.f32.tf32.tf32.f32 "
        "{%0,%1,%2,%3}, {%4,%5,%6,%7}, {%8,%9}, {%0,%1,%2,%3};\n"
        : "+f"(c[0]), "+f"(c[1]), "+f"(c[2]), "+f"(c[3])
        : "r"(a[0]), "r"(a[1]), "r"(a[2]), "r"(a[3]), "r"(b0), "r"(b1));
}

__global__ __launch_bounds__(128) void attn_mma(
    const float* __restrict__ QKVg, const float* __restrict__ alibi,
    const float* __restrict__ amask, float* __restrict__ Og)
{
    extern __shared__ float smn[];
    float* sK = smn;              // [64][132]
    float* sV = smn + 64 * KST;   // [64][136]
    float* sP = sV + 64 * VST;    // [64][68]
    float* sQ = smn;              // alias over sK (temp, consumed before loop)

    const int tid  = threadIdx.x;
    const int lane = tid & 31;
    const int w    = tid >> 5;
    const int g    = lane >> 2;
    const int l    = lane & 3;
    const int bh   = blockIdx.y;
    const int b    = bh >> 4;
    const int h    = bh & 15;
    const int kvh  = h >> 2;
    // heavy blocks first (largest q0 launched earliest)
    const int bxr  = gridDim.x - 1 - blockIdx.x;
    const int q0   = bxr * 64;
    const int ktiles = bxr + 1;

    // ---- load Q tile (64 x 128) to smem, then to A-fragment registers ----
    for (int i = tid; i < 64 * 32; i += 128) {
        int r = i >> 5, c4 = (i & 31) << 2;
        *(float4*)&sQ[r * KST + c4] =
            *(const float4*)&QKVg[(size_t)(b * SS + q0 + r) * QKVD + h * HD + c4];
    }
    __syncthreads();

    unsigned qf[16][4];
    #pragma unroll
    for (int kc = 0; kc < 16; kc++) {
        const float* p = sQ + (w * 16 + g) * KST + kc * 8 + l;
        qf[kc][0] = tf32u(p[0]);
        qf[kc][1] = tf32u(p[8 * KST]);
        qf[kc][2] = tf32u(p[4]);
        qf[kc][3] = tf32u(p[8 * KST + 4]);
    }
    __syncthreads();

    const float L2E = 1.4426950408889634f;
    const float SCL = 0.08838834764831845f * L2E;  // 1/sqrt(128) * log2(e)

    float m0 = -1e30f, m1 = -1e30f, s0 = 0.f, s1 = 0.f;
    float o[16][4];
    #pragma unroll
    for (int i = 0; i < 16; i++)
        #pragma unroll
        for (int j = 0; j < 4; j++) o[i][j] = 0.f;

    const int qrow = q0 + w * 16 + g;   // this lane's first q row (global in seq)

    for (int kt = 0; kt < ktiles; kt++) {
        const int k0 = kt * 64;

        // ---- cooperative load K, V tiles (tf32-rounded) ----
        for (int i = tid; i < 64 * 32; i += 128) {
            int r = i >> 5, c4 = (i & 31) << 2;
            size_t rowbase = (size_t)(b * SS + k0 + r) * QKVD + kvh * HD + c4;
            float4 kv = *(const float4*)&QKVg[rowbase + KOFF];
            kv.x = tf32f(kv.x); kv.y = tf32f(kv.y);
            kv.z = tf32f(kv.z); kv.w = tf32f(kv.w);
            *(float4*)&sK[r * KST + c4] = kv;
            float4 vv = *(const float4*)&QKVg[rowbase + VOFF];
            vv.x = tf32f(vv.x); vv.y = tf32f(vv.y);
            vv.z = tf32f(vv.z); vv.w = tf32f(vv.w);
            *(float4*)&sV[r * VST + c4] = vv;
        }
        __syncthreads();

        // ---- QK^T: scores 16x64 per warp ----
        float sc[8][4];
        #pragma unroll
        for (int nb = 0; nb < 8; nb++)
            #pragma unroll
            for (int j = 0; j < 4; j++) sc[nb][j] = 0.f;

        #pragma unroll
        for (int kc = 0; kc < 16; kc++) {
            #pragma unroll
            for (int nb = 0; nb < 8; nb++) {
                unsigned b0 = __float_as_uint(sK[(nb * 8 + g) * KST + kc * 8 + l]);
                unsigned b1 = __float_as_uint(sK[(nb * 8 + g) * KST + kc * 8 + l + 4]);
                mma8(sc[nb], qf[kc], b0, b1);
            }
        }

        // ---- scale + alibi + mask + causal, in log2 domain ----
        const bool diag = (k0 == q0);
        float mx0 = -1e30f, mx1 = -1e30f;
        {
            const float* alr = &alibi[((size_t)b * SS + qrow) * SS + k0 + 2 * l];
            const float* amr = &amask[b * SS + k0 + 2 * l];
            #pragma unroll
            for (int nb = 0; nb < 8; nb++) {
                float2 amv = *(const float2*)(amr + nb * 8);
                float2 al0 = *(const float2*)(alr + nb * 8);
                float2 al1 = *(const float2*)(alr + nb * 8 + 8 * SS);
                sc[nb][0] = sc[nb][0] * SCL + (al0.x + amv.x) * L2E;
                sc[nb][1] = sc[nb][1] * SCL + (al0.y + amv.y) * L2E;
                sc[nb][2] = sc[nb][2] * SCL + (al1.x + amv.x) * L2E;
                sc[nb][3] = sc[nb][3] * SCL + (al1.y + amv.y) * L2E;
                if (diag) {
                    int kc0 = k0 + nb * 8 + 2 * l;
                    if (kc0     > qrow)     sc[nb][0] = -1e9f;
                    if (kc0 + 1 > qrow)     sc[nb][1] = -1e9f;
                    if (kc0     > qrow + 8) sc[nb][2] = -1e9f;
                    if (kc0 + 1 > qrow + 8) sc[nb][3] = -1e9f;
                }
                mx0 = fmaxf(mx0, fmaxf(sc[nb][0], sc[nb][1]));
                mx1 = fmaxf(mx1, fmaxf(sc[nb][2], sc[nb][3]));
            }
        }

        // row max across the quad (lanes sharing rows)
        mx0 = fmaxf(mx0, __shfl_xor_sync(0xffffffffu, mx0, 1));
        mx0 = fmaxf(mx0, __shfl_xor_sync(0xffffffffu, mx0, 2));
        mx1 = fmaxf(mx1, __shfl_xor_sync(0xffffffffu, mx1, 1));
        mx1 = fmaxf(mx1, __shfl_xor_sync(0xffffffffu, mx1, 2));

        float mn0 = fmaxf(m0, mx0), mn1 = fmaxf(m1, mx1);
        float c0 = ex2(m0 - mn0), c1 = ex2(m1 - mn1);
        m0 = mn0; m1 = mn1;

        // ---- p = 2^(sc - m), row sums, store P (tf32) ----
        float rs0 = 0.f, rs1 = 0.f;
        #pragma unroll
        for (int nb = 0; nb < 8; nb++) {
            float p00 = ex2(sc[nb][0] - m0);
            float p01 = ex2(sc[nb][1] - m0);
            float p10 = ex2(sc[nb][2] - m1);
            float p11 = ex2(sc[nb][3] - m1);
            rs0 += p00 + p01;
            rs1 += p10 + p11;
            *(float2*)&sP[(w * 16 + g)     * PST + nb * 8 + 2 * l] =
                make_float2(tf32f(p00), tf32f(p01));
            *(float2*)&sP[(w * 16 + g + 8) * PST + nb * 8 + 2 * l] =
                make_float2(tf32f(p10), tf32f(p11));
        }
        rs0 += __shfl_xor_sync(0xffffffffu, rs0, 1);
        rs0 += __shfl_xor_sync(0xffffffffu, rs0, 2);
        rs1 += __shfl_xor_sync(0xffffffffu, rs1, 1);
        rs1 += __shfl_xor_sync(0xffffffffu, rs1, 2);
        s0 = s0 * c0 + rs0;
        s1 = s1 * c1 + rs1;

        // rescale O
        #pragma unroll
        for (int nb = 0; nb < 16; nb++) {
            o[nb][0] *= c0; o[nb][1] *= c0;
            o[nb][2] *= c1; o[nb][3] *= c1;
        }
        __syncwarp();

        // ---- O += P @ V ----
        #pragma unroll
        for (int kc = 0; kc < 8; kc++) {
            unsigned a[4];
            a[0] = __float_as_uint(sP[(w * 16 + g)     * PST + kc * 8 + l]);
            a[1] = __float_as_uint(sP[(w * 16 + g + 8) * PST + kc * 8 + l]);
            a[2] = __float_as_uint(sP[(w * 16 + g)     * PST + kc * 8 + l + 4]);
            a[3] = __float_as_uint(sP[(w * 16 + g + 8) * PST + kc * 8 + l + 4]);
            #pragma unroll
            for (int nb = 0; nb < 16; nb++) {
                unsigned b0 = __float_as_uint(sV[(kc * 8 + l)     * VST + nb * 8 + g]);
                unsigned b1 = __float_as_uint(sV[(kc * 8 + l + 4) * VST + nb * 8 + g]);
                mma8(o[nb], a, b0, b1);
            }
        }
        __syncthreads();   // all reads of sK/sV done before next tile's loads
    }

    // ---- epilogue: O /= l, round to tf32 (feeds Wo gemm), write ctx ----
    float inv0 = 1.0f / s0, inv1 = 1.0f / s1;
    size_t row0 = (size_t)(b * SS + qrow);
    #pragma unroll
    for (int nb = 0; nb < 16; nb++) {
        int col = h * HD + nb * 8 + 2 * l;
        *(float2*)&Og[row0 * DIM + col] =
            make_float2(tf32f(o[nb][0] * inv0), tf32f(o[nb][1] * inv0));
        *(float2*)&Og[(row0 + 8) * DIM + col] =
            make_float2(tf32f(o[nb][2] * inv1), tf32f(o[nb][3] * inv1));
    }
}

// ---------------------------------------------------------------------------
// Launch
// ---------------------------------------------------------------------------
extern "C" void kernel_launch(void* const* d_in, const int* in_sizes, int n_in,
                              void* d_out, int out_size)
{
    const float* X     = (const float*)d_in[0];
    const float* cosT  = (const float*)d_in[1];
    const float* sinT  = (const float*)d_in[2];
    const float* alibi = (const float*)d_in[3];
    const float* amask = (const float*)d_in[4];
    const float* wq    = (const float*)d_in[5];
    const float* wk    = (const float*)d_in[6];
    const float* wv    = (const float*)d_in[7];
    const float* wo    = (const float*)d_in[8];
    float* out = (float*)d_out;

    float *Xr, *Wqkv, *Wor, *QKV, *C;
    cudaGetSymbolAddress((void**)&Xr,   gXr);
    cudaGetSymbolAddress((void**)&Wqkv, gWqkv);
    cudaGetSymbolAddress((void**)&Wor,  gWor);
    cudaGetSymbolAddress((void**)&QKV,  gQKV);
    cudaGetSymbolAddress((void**)&C,    gC);

    cudaFuncSetAttribute(tf32_gemm,
                         cudaFuncAttributeMaxDynamicSharedMemorySize, GEMM_SMEM);
    cudaFuncSetAttribute(attn_mma,
                         cudaFuncAttributeMaxDynamicSharedMemorySize, ATTN_SMEM);

    // tf32 rounding / weight packing
    round_tf32_k<<<(ROWS*DIM/4 + 255)/256, 256>>>(X, Xr, ROWS*DIM/4);
    pack_wqkv<<<(DIM*QKVD/4 + 255)/256, 256>>>(wq, wk, wv, Wqkv);
    round_tf32_k<<<(DIM*DIM/4 + 255)/256, 256>>>(wo, Wor, DIM*DIM/4);

    // fused QKV projection
    tf32_gemm<<<dim3(QKVD/128, ROWS/128), 256, GEMM_SMEM>>>(Xr, Wqkv, QKV, QKVD, DIM);

    // RoPE on Q (16 heads) and K (4 heads), strided layout
    rope_kernel<<<(ROWS*NH*64 + 255)/256, 256>>>(QKV, cosT, sinT, 4, QKVD);
    rope_kernel<<<(ROWS*KVH*64 + 255)/256, 256>>>(QKV + KOFF, cosT, sinT, 2, QKVD);

    // tensor-core flash attention
    attn_mma<<<dim3(SS/64, BB*NH), 128, ATTN_SMEM>>>(QKV, alibi, amask, C);

    // output projection
    tf32_gemm<<<dim3(DIM/128, ROWS/128), 256, GEMM_SMEM>>>(C, Wor, out, DIM, DIM);
}

// round 4
// speedup vs baseline: 4.9196x; 1.0501x over previous
#include <cuda_runtime.h>
#include <cstdint>

// Problem constants
#define BB   2
#define SS   2048
#define DIM  2048
#define NH   16
#define KVH  4
#define HD   128
#define ROWS (BB*SS)          // 4096
#define QKVD 3072             // fused Q|K|V width
#define KOFF 2048
#define VOFF 2560

// ---------------------------------------------------------------------------
// Scratch (static device globals — no allocation)
// ---------------------------------------------------------------------------
__device__ float gXr [(size_t)ROWS * DIM];    // X, tf32, K-permuted
__device__ float gWt [(size_t)QKVD * DIM];    // [Wq|Wk|Wv]^T, tf32, K-permuted
__device__ float gWot[(size_t)DIM * DIM];     // Wo^T, tf32, K-permuted
__device__ float gQKV[(size_t)ROWS * QKVD];   // normal layout
__device__ float gC  [(size_t)ROWS * DIM];    // attn ctx, tf32, K-permuted

// ---------------------------------------------------------------------------
// helpers
// ---------------------------------------------------------------------------
__device__ __forceinline__ unsigned tf32u(float x) {
    unsigned u;
    asm("cvt.rna.tf32.f32 %0, %1;" : "=r"(u) : "f"(x));
    return u;
}
__device__ __forceinline__ float tf32f(float x) { return __uint_as_float(tf32u(x)); }
__device__ __forceinline__ float ex2(float x) {
    float r;
    asm("ex2.approx.ftz.f32 %0, %1;" : "=f"(r) : "f"(x));
    return r;
}

// Permute X into gXr: within each 8-col group store {c0,c4,c1,c5,c2,c6,c3,c7}
__global__ void permute_round_x(const float* __restrict__ in,
                                float* __restrict__ out) {
    int idx = blockIdx.x * blockDim.x + threadIdx.x;   // one 8-group
    if (idx >= ROWS * (DIM / 8)) return;
    const float* s = in + (size_t)idx * 8;
    float4 v0 = *(const float4*)s;
    float4 v1 = *(const float4*)(s + 4);
    float* d = out + (size_t)idx * 8;
    *(float4*)d = make_float4(tf32f(v0.x), tf32f(v1.x), tf32f(v0.y), tf32f(v1.y));
    *(float4*)(d + 4) = make_float4(tf32f(v0.z), tf32f(v1.z), tf32f(v0.w), tf32f(v1.w));
}

// Transpose-pack W[k][n] -> out[n][k_permuted], tf32. block (32,8).
__global__ void wpack_t(const float* __restrict__ W, float* __restrict__ out,
                        int Nw) {
    __shared__ float t[32][33];
    int tx = threadIdx.x, ty = threadIdx.y;
    int k0 = blockIdx.y * 32, n0 = blockIdx.x * 32;
    #pragma unroll
    for (int i = 0; i < 4; i++)
        t[ty + 8 * i][tx] = W[(size_t)(k0 + ty + 8 * i) * Nw + n0 + tx];
    __syncthreads();
    int grp = tx >> 3, pos = tx & 7;
    int ksrc = grp * 8 + ((pos >> 1) | ((pos & 1) << 2));
    #pragma unroll
    for (int i = 0; i < 4; i++)
        out[(size_t)(n0 + ty + 8 * i) * 2048 + k0 + tx] = tf32f(t[ksrc][ty + 8 * i]);
}

// ---------------------------------------------------------------------------
// TF32 GEMM v2: C[M,N] = A[M,K] @ Bt[N,K]^T.  A,Bt K-major, K-permuted.
// 128x128 block, 4 warps (2x2), warp tile 64x64, BK=32, cp.async dbuf.
// Fragment loads are LDS.64 (stride 40 -> conflict-free per half-warp).
// ---------------------------------------------------------------------------
#define GST 40
#define GEMM2_SMEM (2 * 2 * 128 * GST * 4)   // 81920 B

__device__ __forceinline__ void cp16(unsigned dst, const void* src) {
    asm volatile("cp.async.cg.shared.global [%0], [%1], 16;\n"
                 :: "r"(dst), "l"(src));
}

__device__ __forceinline__ void mma8(float* c, const unsigned* a,
                                     unsigned b0, unsigned b1) {
    asm volatile(
        "mma.sync.aligned.m16n8k8.row.col.f32.tf32.tf32.f32 "
        "{%0,%1,%2,%3}, {%4,%5,%6,%7}, {%8,%9}, {%0,%1,%2,%3};\n"
        : "+f"(c[0]), "+f"(c[1]), "+f"(c[2]), "+f"(c[3])
        : "r"(a[0]), "r"(a[1]), "r"(a[2]), "r"(a[3]), "r"(b0), "r"(b1));
}

__global__ __launch_bounds__(128) void tf32_gemm2(
    const float* __restrict__ A, const float* __restrict__ Bt,
    float* __restrict__ C, int N, int K)
{
    extern __shared__ float sm[];
    float* As = sm;                    // [2][128][GST]
    float* Bs = sm + 2 * 128 * GST;    // [2][128][GST]

    const int tid  = threadIdx.x;
    const int lane = tid & 31;
    const int w    = tid >> 5;
    const int g    = lane >> 2;
    const int l    = lane & 3;
    const int wm   = (w >> 1) * 64;
    const int wn   = (w & 1) * 64;
    const long bm  = (long)blockIdx.y * 128;
    const long bn  = (long)blockIdx.x * 128;

    const unsigned sAu = (unsigned)__cvta_generic_to_shared(As);
    const unsigned sBu = (unsigned)__cvta_generic_to_shared(Bs);

    // coalesced fill mapping: 8 lanes cover one row's 128B
    const int frow = tid >> 3;            // 0..15 (+16*p)
    const int fcol = (tid & 7) << 2;      // 0,4,..,28
    const float* Abase = A  + (bm + frow) * K + fcol;
    const float* Bbase = Bt + (bn + frow) * K + fcol;

    float acc[4][8][4];
    #pragma unroll
    for (int mt = 0; mt < 4; mt++)
        #pragma unroll
        for (int nt = 0; nt < 8; nt++)
            #pragma unroll
            for (int j = 0; j < 4; j++) acc[mt][nt][j] = 0.f;

    const int niter = K / 32;

    auto issue = [&](int it, int buf) {
        long k0 = (long)it * 32;
        #pragma unroll
        for (int p = 0; p < 8; p++)
            cp16(sAu + (unsigned)(((buf * 128 + frow + p * 16) * GST + fcol) * 4),
                 Abase + (long)p * 16 * K + k0);
        #pragma unroll
        for (int p = 0; p < 8; p++)
            cp16(sBu + (unsigned)(((buf * 128 + frow + p * 16) * GST + fcol) * 4),
                 Bbase + (long)p * 16 * K + k0);
        asm volatile("cp.async.commit_group;\n");
    };

    issue(0, 0);

    for (int it = 0; it < niter; it++) {
        const int buf = it & 1;
        if (it + 1 < niter) {
            issue(it + 1, buf ^ 1);
            asm volatile("cp.async.wait_group 1;\n");
        } else {
            asm volatile("cp.async.wait_group 0;\n");
        }
        __syncthreads();

        const float* Ab = As + buf * 128 * GST;
        const float* Bb = Bs + buf * 128 * GST;

        #pragma unroll
        for (int kk = 0; kk < 4; kk++) {
            float2 av[4][2];
            float2 bv[8];
            #pragma unroll
            for (int mt = 0; mt < 4; mt++) {
                av[mt][0] = *(const float2*)&Ab[(wm + mt * 16 + g)     * GST + kk * 8 + 2 * l];
                av[mt][1] = *(const float2*)&Ab[(wm + mt * 16 + g + 8) * GST + kk * 8 + 2 * l];
            }
            #pragma unroll
            for (int nt = 0; nt < 8; nt++)
                bv[nt] = *(const float2*)&Bb[(wn + nt * 8 + g) * GST + kk * 8 + 2 * l];

            #pragma unroll
            for (int mt = 0; mt < 4; mt++) {
                unsigned a[4];
                a[0] = __float_as_uint(av[mt][0].x);
                a[1] = __float_as_uint(av[mt][1].x);
                a[2] = __float_as_uint(av[mt][0].y);
                a[3] = __float_as_uint(av[mt][1].y);
                #pragma unroll
                for (int nt = 0; nt < 8; nt++)
                    mma8(acc[mt][nt], a,
                         __float_as_uint(bv[nt].x), __float_as_uint(bv[nt].y));
            }
        }
        __syncthreads();
    }

    // epilogue (normal layout output)
    #pragma unroll
    for (int mt = 0; mt < 4; mt++)
        #pragma unroll
        for (int nt = 0; nt < 8; nt++) {
            const float* c = acc[mt][nt];
            long row = bm + wm + mt * 16 + g;
            long col = bn + wn + nt * 8 + 2 * l;
            *(float2*)&C[row * N + col]       = make_float2(c[0], c[1]);
            *(float2*)&C[(row + 8) * N + col] = make_float2(c[2], c[3]);
        }
}

// ---------------------------------------------------------------------------
// RoPE in-place, strided buffer (gQKV normal layout)
// ---------------------------------------------------------------------------
__global__ void rope_kernel(float* __restrict__ x,
                            const float* __restrict__ cosT,
                            const float* __restrict__ sinT,
                            int nh_shift, int stride)
{
    int idx = blockIdx.x * blockDim.x + threadIdx.x;
    int nheads = 1 << nh_shift;
    int total = ROWS * nheads * 64;
    if (idx >= total) return;
    int d = idx & 63;
    int h = (idx >> 6) & (nheads - 1);
    int r = idx >> (6 + nh_shift);
    int s = r & (SS - 1);

    float c0 = cosT[s * HD + d];
    float s0 = sinT[s * HD + d];
    float c1 = cosT[s * HD + d + 64];
    float s1 = sinT[s * HD + d + 64];

    float* p = x + (size_t)r * stride + h * HD;
    float x0 = p[d];
    float x1 = p[d + 64];
    p[d]      = x0 * c0 - x1 * s0;
    p[d + 64] = x1 * c1 + x0 * s1;
}

// ---------------------------------------------------------------------------
// Tensor-core flash attention (unchanged core; epilogue writes K-permuted C)
// ---------------------------------------------------------------------------
#define KST 132
#define VST 136
#define PST 68
#define ATTN_SMEM ((64*KST + 64*VST + 64*PST) * 4)   // 86016 B

__global__ __launch_bounds__(128) void attn_mma(
    const float* __restrict__ QKVg, const float* __restrict__ alibi,
    const float* __restrict__ amask, float* __restrict__ Og)
{
    extern __shared__ float smn[];
    float* sK = smn;              // [64][132]
    float* sV = smn + 64 * KST;   // [64][136]
    float* sP = sV + 64 * VST;    // [64][68]
    float* sQ = smn;              // alias over sK (temp, consumed before loop)

    const int tid  = threadIdx.x;
    const int lane = tid & 31;
    const int w    = tid >> 5;
    const int g    = lane >> 2;
    const int l    = lane & 3;
    const int bh   = blockIdx.y;
    const int b    = bh >> 4;
    const int h    = bh & 15;
    const int kvh  = h >> 2;
    const int bxr  = gridDim.x - 1 - blockIdx.x;
    const int q0   = bxr * 64;
    const int ktiles = bxr + 1;

    for (int i = tid; i < 64 * 32; i += 128) {
        int r = i >> 5, c4 = (i & 31) << 2;
        *(float4*)&sQ[r * KST + c4] =
            *(const float4*)&QKVg[(size_t)(b * SS + q0 + r) * QKVD + h * HD + c4];
    }
    __syncthreads();

    unsigned qf[16][4];
    #pragma unroll
    for (int kc = 0; kc < 16; kc++) {
        const float* p = sQ + (w * 16 + g) * KST + kc * 8 + l;
        qf[kc][0] = tf32u(p[0]);
        qf[kc][1] = tf32u(p[8 * KST]);
        qf[kc][2] = tf32u(p[4]);
        qf[kc][3] = tf32u(p[8 * KST + 4]);
    }
    __syncthreads();

    const float L2E = 1.4426950408889634f;
    const float SCL = 0.08838834764831845f * L2E;

    float m0 = -1e30f, m1 = -1e30f, s0 = 0.f, s1 = 0.f;
    float o[16][4];
    #pragma unroll
    for (int i = 0; i < 16; i++)
        #pragma unroll
        for (int j = 0; j < 4; j++) o[i][j] = 0.f;

    const int qrow = q0 + w * 16 + g;

    for (int kt = 0; kt < ktiles; kt++) {
        const int k0 = kt * 64;

        for (int i = tid; i < 64 * 32; i += 128) {
            int r = i >> 5, c4 = (i & 31) << 2;
            size_t rowbase = (size_t)(b * SS + k0 + r) * QKVD + kvh * HD + c4;
            float4 kv = *(const float4*)&QKVg[rowbase + KOFF];
            kv.x = tf32f(kv.x); kv.y = tf32f(kv.y);
            kv.z = tf32f(kv.z); kv.w = tf32f(kv.w);
            *(float4*)&sK[r * KST + c4] = kv;
            float4 vv = *(const float4*)&QKVg[rowbase + VOFF];
            vv.x = tf32f(vv.x); vv.y = tf32f(vv.y);
            vv.z = tf32f(vv.z); vv.w = tf32f(vv.w);
            *(float4*)&sV[r * VST + c4] = vv;
        }
        __syncthreads();

        float sc[8][4];
        #pragma unroll
        for (int nb = 0; nb < 8; nb++)
            #pragma unroll
            for (int j = 0; j < 4; j++) sc[nb][j] = 0.f;

        #pragma unroll
        for (int kc = 0; kc < 16; kc++) {
            #pragma unroll
            for (int nb = 0; nb < 8; nb++) {
                unsigned b0 = __float_as_uint(sK[(nb * 8 + g) * KST + kc * 8 + l]);
                unsigned b1 = __float_as_uint(sK[(nb * 8 + g) * KST + kc * 8 + l + 4]);
                mma8(sc[nb], qf[kc], b0, b1);
            }
        }

        const bool diag = (k0 == q0);
        float mx0 = -1e30f, mx1 = -1e30f;
        {
            const float* alr = &alibi[((size_t)b * SS + qrow) * SS + k0 + 2 * l];
            const float* amr = &amask[b * SS + k0 + 2 * l];
            #pragma unroll
            for (int nb = 0; nb < 8; nb++) {
                float2 amv = *(const float2*)(amr + nb * 8);
                float2 al0 = *(const float2*)(alr + nb * 8);
                float2 al1 = *(const float2*)(alr + nb * 8 + 8 * SS);
                sc[nb][0] = sc[nb][0] * SCL + (al0.x + amv.x) * L2E;
                sc[nb][1] = sc[nb][1] * SCL + (al0.y + amv.y) * L2E;
                sc[nb][2] = sc[nb][2] * SCL + (al1.x + amv.x) * L2E;
                sc[nb][3] = sc[nb][3] * SCL + (al1.y + amv.y) * L2E;
                if (diag) {
                    int kc0 = k0 + nb * 8 + 2 * l;
                    if (kc0     > qrow)     sc[nb][0] = -1e9f;
                    if (kc0 + 1 > qrow)     sc[nb][1] = -1e9f;
                    if (kc0     > qrow + 8) sc[nb][2] = -1e9f;
                    if (kc0 + 1 > qrow + 8) sc[nb][3] = -1e9f;
                }
                mx0 = fmaxf(mx0, fmaxf(sc[nb][0], sc[nb][1]));
                mx1 = fmaxf(mx1, fmaxf(sc[nb][2], sc[nb][3]));
            }
        }

        mx0 = fmaxf(mx0, __shfl_xor_sync(0xffffffffu, mx0, 1));
        mx0 = fmaxf(mx0, __shfl_xor_sync(0xffffffffu, mx0, 2));
        mx1 = fmaxf(mx1, __shfl_xor_sync(0xffffffffu, mx1, 1));
        mx1 = fmaxf(mx1, __shfl_xor_sync(0xffffffffu, mx1, 2));

        float mn0 = fmaxf(m0, mx0), mn1 = fmaxf(m1, mx1);
        float c0 = ex2(m0 - mn0), c1 = ex2(m1 - mn1);
        m0 = mn0; m1 = mn1;

        float rs0 = 0.f, rs1 = 0.f;
        #pragma unroll
        for (int nb = 0; nb < 8; nb++) {
            float p00 = ex2(sc[nb][0] - m0);
            float p01 = ex2(sc[nb][1] - m0);
            float p10 = ex2(sc[nb][2] - m1);
            float p11 = ex2(sc[nb][3] - m1);
            rs0 += p00 + p01;
            rs1 += p10 + p11;
            *(float2*)&sP[(w * 16 + g)     * PST + nb * 8 + 2 * l] =
                make_float2(tf32f(p00), tf32f(p01));
            *(float2*)&sP[(w * 16 + g + 8) * PST + nb * 8 + 2 * l] =
                make_float2(tf32f(p10), tf32f(p11));
        }
        rs0 += __shfl_xor_sync(0xffffffffu, rs0, 1);
        rs0 += __shfl_xor_sync(0xffffffffu, rs0, 2);
        rs1 += __shfl_xor_sync(0xffffffffu, rs1, 1);
        rs1 += __shfl_xor_sync(0xffffffffu, rs1, 2);
        s0 = s0 * c0 + rs0;
        s1 = s1 * c1 + rs1;

        #pragma unroll
        for (int nb = 0; nb < 16; nb++) {
            o[nb][0] *= c0; o[nb][1] *= c0;
            o[nb][2] *= c1; o[nb][3] *= c1;
        }
        __syncwarp();

        #pragma unroll
        for (int kc = 0; kc < 8; kc++) {
            unsigned a[4];
            a[0] = __float_as_uint(sP[(w * 16 + g)     * PST + kc * 8 + l]);
            a[1] = __float_as_uint(sP[(w * 16 + g + 8) * PST + kc * 8 + l]);
            a[2] = __float_as_uint(sP[(w * 16 + g)     * PST + kc * 8 + l + 4]);
            a[3] = __float_as_uint(sP[(w * 16 + g + 8) * PST + kc * 8 + l + 4]);
            #pragma unroll
            for (int nb = 0; nb < 16; nb++) {
                unsigned b0 = __float_as_uint(sV[(kc * 8 + l)     * VST + nb * 8 + g]);
                unsigned b1 = __float_as_uint(sV[(kc * 8 + l + 4) * VST + nb * 8 + g]);
                mma8(o[nb], a, b0, b1);
            }
        }
        __syncthreads();
    }

    // epilogue: O /= l, tf32-round, write K-PERMUTED ctx (A-operand of Wo).
    // orig col j within 8-group goes to position p(j)=2*(j&3)+((j>>2)&1):
    // thread holds j = 2l, 2l+1 -> positions pos0, pos0+2.
    float inv0 = 1.0f / s0, inv1 = 1.0f / s1;
    size_t row0 = (size_t)(b * SS + qrow);
    const int pos0 = (l < 2) ? 4 * l : 4 * l - 7;
    #pragma unroll
    for (int nb = 0; nb < 16; nb++) {
        size_t cb = h * HD + nb * 8;
        Og[row0 * DIM + cb + pos0]           = tf32f(o[nb][0] * inv0);
        Og[row0 * DIM + cb + pos0 + 2]       = tf32f(o[nb][1] * inv0);
        Og[(row0 + 8) * DIM + cb + pos0]     = tf32f(o[nb][2] * inv1);
        Og[(row0 + 8) * DIM + cb + pos0 + 2] = tf32f(o[nb][3] * inv1);
    }
}

// ---------------------------------------------------------------------------
// Launch
// ---------------------------------------------------------------------------
extern "C" void kernel_launch(void* const* d_in, const int* in_sizes, int n_in,
                              void* d_out, int out_size)
{
    const float* X     = (const float*)d_in[0];
    const float* cosT  = (const float*)d_in[1];
    const float* sinT  = (const float*)d_in[2];
    const float* alibi = (const float*)d_in[3];
    const float* amask = (const float*)d_in[4];
    const float* wq    = (const float*)d_in[5];
    const float* wk    = (const float*)d_in[6];
    const float* wv    = (const float*)d_in[7];
    const float* wo    = (const float*)d_in[8];
    float* out = (float*)d_out;

    float *Xr, *Wt, *Wot, *QKV, *C;
    cudaGetSymbolAddress((void**)&Xr,  gXr);
    cudaGetSymbolAddress((void**)&Wt,  gWt);
    cudaGetSymbolAddress((void**)&Wot, gWot);
    cudaGetSymbolAddress((void**)&QKV, gQKV);
    cudaGetSymbolAddress((void**)&C,   gC);

    cudaFuncSetAttribute(tf32_gemm2,
                         cudaFuncAttributeMaxDynamicSharedMemorySize, GEMM2_SMEM);
    cudaFuncSetAttribute(attn_mma,
                         cudaFuncAttributeMaxDynamicSharedMemorySize, ATTN_SMEM);

    // pack: permute+round X; transpose+permute+round weights
    permute_round_x<<<ROWS * (DIM / 8) / 256, 256>>>(X, Xr);
    dim3 tb(32, 8);
    wpack_t<<<dim3(64, 64), tb>>>(wq, Wt, 2048);
    wpack_t<<<dim3(16, 64), tb>>>(wk, Wt + (size_t)2048 * 2048, 512);
    wpack_t<<<dim3(16, 64), tb>>>(wv, Wt + (size_t)2560 * 2048, 512);
    wpack_t<<<dim3(64, 64), tb>>>(wo, Wot, 2048);

    // fused QKV projection
    tf32_gemm2<<<dim3(QKVD / 128, ROWS / 128), 128, GEMM2_SMEM>>>(
        Xr, Wt, QKV, QKVD, DIM);

    // RoPE on Q (16 heads) and K (4 heads)
    rope_kernel<<<(ROWS * NH * 64 + 255) / 256, 256>>>(QKV, cosT, sinT, 4, QKVD);
    rope_kernel<<<(ROWS * KVH * 64 + 255) / 256, 256>>>(QKV + KOFF, cosT, sinT, 2, QKVD);

    // tensor-core flash attention
    attn_mma<<<dim3(SS / 64, BB * NH), 128, ATTN_SMEM>>>(QKV, alibi, amask, C);

    // output projection
    tf32_gemm2<<<dim3(DIM / 128, ROWS / 128), 128, GEMM2_SMEM>>>(
        C, Wot, out, DIM, DIM);
}